// round 14
// baseline (speedup 1.0000x reference)
#include <cuda_runtime.h>
#include <math.h>

#define NREG 36
#define EMBD 1024
#define SIMD 16
#define HIDD 32
#define NKER 8
#define GRID 1332           // 9 CTAs/SM * 148 SMs
#define NWARP (GRID * 4)    // 5328 streaming warps

// Precomputed folded constants (prep_kernel -> main kernel)
__device__ float g_W1f[SIMD * HIDD];  // gsum · w1n^T folded: [d][hh]
__device__ float g_w2s[HIDD];         // weight-normed out2 row / 36
__device__ float g_b1[HIDD];
__device__ float g_b2s;               // out2 bias / 36 (added once per row)

__global__ void prep_kernel(const float* __restrict__ gcn_w,
                            const float* __restrict__ out1_v, const float* __restrict__ out1_g,
                            const float* __restrict__ out1_b, const float* __restrict__ out2_v,
                            const float* __restrict__ out2_g, const float* __restrict__ out2_b)
{
    __shared__ float gs[SIMD * HIDD];
    __shared__ float w1[HIDD * HIDD];
    const int tid = threadIdx.x;  // 512
    {
        float a = 0.f;
        #pragma unroll
        for (int k = 0; k < NKER; k++) a += gcn_w[k * SIMD * HIDD + tid];
        gs[tid] = a;
    }
    if (tid < HIDD) {
        float ss = 0.f;
        #pragma unroll
        for (int h = 0; h < HIDD; h++) { float v = out1_v[tid * HIDD + h]; ss += v * v; }
        const float sc = out1_g[tid] / (sqrtf(ss) + 1e-12f);
        #pragma unroll
        for (int h = 0; h < HIDD; h++) w1[tid * HIDD + h] = out1_v[tid * HIDD + h] * sc;
        g_b1[tid] = out1_b[tid];
    }
    if (tid == 32) {
        float ss = 0.f;
        #pragma unroll
        for (int h = 0; h < HIDD; h++) { float v = out2_v[h]; ss += v * v; }
        const float sc = out2_g[0] / (sqrtf(ss) + 1e-12f);
        #pragma unroll
        for (int h = 0; h < HIDD; h++) g_w2s[h] = out2_v[h] * sc * (1.0f / 36.0f);
        g_b2s = out2_b[0] * (1.0f / 36.0f);
    }
    __syncthreads();
    {
        const int d = tid >> 5, hh = tid & 31;
        float acc = 0.f;
        #pragma unroll
        for (int h = 0; h < HIDD; h++)
            acc = fmaf(gs[d * HIDD + h], w1[hh * HIDD + h], acc);
        g_W1f[d * HIDD + hh] = acc;
    }
}

__device__ __forceinline__ void dot3(float& q, float& n, float& x, const float4 a, const float4 c) {
    q = fmaf(a.x, a.x, q); q = fmaf(a.y, a.y, q); q = fmaf(a.z, a.z, q); q = fmaf(a.w, a.w, q);
    n = fmaf(c.x, c.x, n); n = fmaf(c.y, c.y, n); n = fmaf(c.z, c.z, n); n = fmaf(c.w, c.w, n);
    x = fmaf(a.x, c.x, x); x = fmaf(a.y, c.y, x); x = fmaf(a.z, c.z, x); x = fmaf(a.w, c.w, x);
}

// Persistent row-streaming (R13 core). Change: next-row refill loads are
// PREDICATED on `more` instead of clamped to adv=0 -> the final iteration
// issues no loads, saving 5328 warps * 8KB = 42.6 MB of discarded traffic.
__global__ void __launch_bounds__(128, 9)
simgsmn_main(const float* __restrict__ inp1, const float* __restrict__ inp2,
             float* __restrict__ out, int totRows)
{
    __shared__ float W1fs[SIMD * HIDD];
    __shared__ float w2ss[HIDD];
    __shared__ float b1s[HIDD];
    const int tid  = threadIdx.x;
    const int w    = tid >> 5;
    const int lane = tid & 31;
    const int g    = lane >> 2;     // group owns sim blocks {2g, 2g+1}
    const int c4   = lane & 3;

    #pragma unroll
    for (int r = 0; r < 4; r++) W1fs[tid + r * 128] = g_W1f[tid + r * 128];
    if (tid < HIDD) { w2ss[tid] = g_w2s[tid]; b1s[tid] = g_b1[tid]; }
    __syncthreads();

    int r = blockIdx.x * 4 + w;                       // this warp's first global row
    if (r >= totRows) return;                         // (whole warp uniform)
    const int loff = g * 32 + c4;                     // lane slot within a row (float4 units)
    const float4* p1 = reinterpret_cast<const float4*>(inp1) + (size_t)r * 256 + loff;
    const float4* p2 = reinterpret_cast<const float4*>(inp2) + (size_t)r * 256 + loff;
    const float b2s = g_b2s;
    const size_t ADV = (size_t)NWARP * 256;

    // prologue: first row's first half in flight
    float4 A0 = __ldcs(p1 +  0), C0 = __ldcs(p2 +  0);
    float4 A1 = __ldcs(p1 +  4), C1 = __ldcs(p2 +  4);
    float4 A2 = __ldcs(p1 +  8), C2 = __ldcs(p2 +  8);
    float4 A3 = __ldcs(p1 + 12), C3 = __ldcs(p2 + 12);

    #pragma unroll 1
    while (true) {
        const bool more = (r + NWARP < totRows);
        float aq0 = 0.f, an0 = 0.f, ax0 = 0.f, aq1 = 0.f, an1 = 0.f, ax1 = 0.f;

        // first half: consume slots, refill with this row's second half (always valid)
        { float4 a = A0, c = C0; A0 = __ldcs(p1 + 16); C0 = __ldcs(p2 + 16); dot3(aq0, an0, ax0, a, c); }
        { float4 a = A1, c = C1; A1 = __ldcs(p1 + 20); C1 = __ldcs(p2 + 20); dot3(aq0, an0, ax0, a, c); }
        { float4 a = A2, c = C2; A2 = __ldcs(p1 + 24); C2 = __ldcs(p2 + 24); dot3(aq0, an0, ax0, a, c); }
        { float4 a = A3, c = C3; A3 = __ldcs(p1 + 28); C3 = __ldcs(p2 + 28); dot3(aq0, an0, ax0, a, c); }
        // second half: consume, refill with NEXT row's first half (predicated)
        { float4 a = A0, c = C0; if (more) { A0 = __ldcs(p1 + ADV +  0); C0 = __ldcs(p2 + ADV +  0); } dot3(aq1, an1, ax1, a, c); }
        { float4 a = A1, c = C1; if (more) { A1 = __ldcs(p1 + ADV +  4); C1 = __ldcs(p2 + ADV +  4); } dot3(aq1, an1, ax1, a, c); }
        { float4 a = A2, c = C2; if (more) { A2 = __ldcs(p1 + ADV +  8); C2 = __ldcs(p2 + ADV +  8); } dot3(aq1, an1, ax1, a, c); }
        { float4 a = A3, c = C3; if (more) { A3 = __ldcs(p1 + ADV + 12); C3 = __ldcs(p2 + ADV + 12); } dot3(aq1, an1, ax1, a, c); }

        // reduce within 4-lane group
        #pragma unroll
        for (int m = 1; m < 4; m <<= 1) {
            aq0 += __shfl_xor_sync(0xffffffffu, aq0, m);
            an0 += __shfl_xor_sync(0xffffffffu, an0, m);
            ax0 += __shfl_xor_sync(0xffffffffu, ax0, m);
            aq1 += __shfl_xor_sync(0xffffffffu, aq1, m);
            an1 += __shfl_xor_sync(0xffffffffu, an1, m);
            ax1 += __shfl_xor_sync(0xffffffffu, ax1, m);
        }
        const float sv0 = ax0 / ((sqrtf(aq0) + 1e-8f) * (sqrtf(an0) + 1e-8f));
        const float sv1 = ax1 / ((sqrtf(aq1) + 1e-8f) * (sqrtf(an1) + 1e-8f));

        // ---- inline per-row tail (overlaps next row's in-flight loads) ----
        float acc = b1s[lane];
        #pragma unroll
        for (int d = 0; d < SIMD; d++) {
            const float v = __shfl_sync(0xffffffffu, (d & 1) ? sv1 : sv0, (d >> 1) << 2);
            acc = fmaf(v, W1fs[d * HIDD + lane], acc);
        }
        float part = w2ss[lane] * tanhf(acc);
        #pragma unroll
        for (int m = 1; m < 32; m <<= 1)
            part += __shfl_xor_sync(0xffffffffu, part, m);
        if (lane == 0) atomicAdd(&out[r / NREG], part + b2s);

        if (!more) break;
        p1 += ADV; p2 += ADV;
        r  += NWARP;
    }
}

extern "C" void kernel_launch(void* const* d_in, const int* in_sizes, int n_in,
                              void* d_out, int out_size) {
    const int Bn = in_sizes[0] / (NREG * EMBD);
    const int totRows = Bn * NREG;
    cudaMemsetAsync(d_out, 0, (size_t)out_size * sizeof(float));
    prep_kernel<<<1, 512>>>((const float*)d_in[4], (const float*)d_in[5],
                            (const float*)d_in[6], (const float*)d_in[7],
                            (const float*)d_in[8], (const float*)d_in[9],
                            (const float*)d_in[10]);
    const int grid = (GRID * 4 <= totRows) ? GRID : (totRows + 3) / 4;
    simgsmn_main<<<grid, 128>>>((const float*)d_in[0], (const float*)d_in[1],
                                (float*)d_out, totRows);
}

// round 16
// speedup vs baseline: 1.3449x; 1.3449x over previous
#include <cuda_runtime.h>
#include <math.h>

#define NREG 36
#define EMBD 1024
#define SIMD 16
#define HIDD 32
#define NKER 8
#define GRID 1332           // 9 CTAs/SM * 148 SMs
#define NWARP (GRID * 4)    // 5328 streaming warps

// Precomputed folded constants (prep_kernel -> main kernel)
__device__ float g_W1f[SIMD * HIDD];  // gsum · w1n^T folded: [d][hh]
__device__ float g_w2s[HIDD];         // weight-normed out2 row / 36
__device__ float g_b1[HIDD];
__device__ float g_b2s;               // out2 bias / 36 (added once per row)

__global__ void prep_kernel(const float* __restrict__ gcn_w,
                            const float* __restrict__ out1_v, const float* __restrict__ out1_g,
                            const float* __restrict__ out1_b, const float* __restrict__ out2_v,
                            const float* __restrict__ out2_g, const float* __restrict__ out2_b)
{
    __shared__ float gs[SIMD * HIDD];
    __shared__ float w1[HIDD * HIDD];
    const int tid = threadIdx.x;  // 512
    {
        float a = 0.f;
        #pragma unroll
        for (int k = 0; k < NKER; k++) a += gcn_w[k * SIMD * HIDD + tid];
        gs[tid] = a;
    }
    if (tid < HIDD) {
        float ss = 0.f;
        #pragma unroll
        for (int h = 0; h < HIDD; h++) { float v = out1_v[tid * HIDD + h]; ss += v * v; }
        const float sc = out1_g[tid] / (sqrtf(ss) + 1e-12f);
        #pragma unroll
        for (int h = 0; h < HIDD; h++) w1[tid * HIDD + h] = out1_v[tid * HIDD + h] * sc;
        g_b1[tid] = out1_b[tid];
    }
    if (tid == 32) {
        float ss = 0.f;
        #pragma unroll
        for (int h = 0; h < HIDD; h++) { float v = out2_v[h]; ss += v * v; }
        const float sc = out2_g[0] / (sqrtf(ss) + 1e-12f);
        #pragma unroll
        for (int h = 0; h < HIDD; h++) g_w2s[h] = out2_v[h] * sc * (1.0f / 36.0f);
        g_b2s = out2_b[0] * (1.0f / 36.0f);
    }
    __syncthreads();
    {
        const int d = tid >> 5, hh = tid & 31;
        float acc = 0.f;
        #pragma unroll
        for (int h = 0; h < HIDD; h++)
            acc = fmaf(gs[d * HIDD + h], w1[hh * HIDD + h], acc);
        g_W1f[d * HIDD + hh] = acc;
    }
}

__device__ __forceinline__ void dot3(float& q, float& n, float& x, const float4 a, const float4 c) {
    q = fmaf(a.x, a.x, q); q = fmaf(a.y, a.y, q); q = fmaf(a.z, a.z, q); q = fmaf(a.w, a.w, q);
    n = fmaf(c.x, c.x, n); n = fmaf(c.y, c.y, n); n = fmaf(c.z, c.z, n); n = fmaf(c.w, c.w, n);
    x = fmaf(a.x, c.x, x); x = fmaf(a.y, c.y, x); x = fmaf(a.z, c.z, x); x = fmaf(a.w, c.w, x);
}

// Persistent row-streaming (R13 core, unconditional refills with constant ADV)
// + PEELED final iteration (no refill loads) instead of predication/clamping.
__global__ void __launch_bounds__(128, 9)
simgsmn_main(const float* __restrict__ inp1, const float* __restrict__ inp2,
             float* __restrict__ out, int totRows)
{
    __shared__ float W1fs[SIMD * HIDD];
    __shared__ float w2ss[HIDD];
    __shared__ float b1s[HIDD];
    const int tid  = threadIdx.x;
    const int w    = tid >> 5;
    const int lane = tid & 31;
    const int g    = lane >> 2;     // group owns sim blocks {2g, 2g+1}
    const int c4   = lane & 3;

    #pragma unroll
    for (int r = 0; r < 4; r++) W1fs[tid + r * 128] = g_W1f[tid + r * 128];
    if (tid < HIDD) { w2ss[tid] = g_w2s[tid]; b1s[tid] = g_b1[tid]; }
    __syncthreads();

    int r = blockIdx.x * 4 + w;                       // this warp's first global row
    if (r >= totRows) return;                         // (whole warp uniform)
    const int loff = g * 32 + c4;                     // lane slot within a row (float4 units)
    const float4* p1 = reinterpret_cast<const float4*>(inp1) + (size_t)r * 256 + loff;
    const float4* p2 = reinterpret_cast<const float4*>(inp2) + (size_t)r * 256 + loff;
    const float b2s = g_b2s;
    const size_t ADV = (size_t)NWARP * 256;

    // prologue: first row's first half in flight
    float4 A0 = __ldcs(p1 +  0), C0 = __ldcs(p2 +  0);
    float4 A1 = __ldcs(p1 +  4), C1 = __ldcs(p2 +  4);
    float4 A2 = __ldcs(p1 +  8), C2 = __ldcs(p2 +  8);
    float4 A3 = __ldcs(p1 + 12), C3 = __ldcs(p2 + 12);

    float aq0, an0, ax0, aq1, an1, ax1;

    // ---- hot loop: all iterations except the last; refills unconditional ----
    #pragma unroll 1
    while (r + NWARP < totRows) {
        aq0 = 0.f; an0 = 0.f; ax0 = 0.f; aq1 = 0.f; an1 = 0.f; ax1 = 0.f;

        { float4 a = A0, c = C0; A0 = __ldcs(p1 + 16); C0 = __ldcs(p2 + 16); dot3(aq0, an0, ax0, a, c); }
        { float4 a = A1, c = C1; A1 = __ldcs(p1 + 20); C1 = __ldcs(p2 + 20); dot3(aq0, an0, ax0, a, c); }
        { float4 a = A2, c = C2; A2 = __ldcs(p1 + 24); C2 = __ldcs(p2 + 24); dot3(aq0, an0, ax0, a, c); }
        { float4 a = A3, c = C3; A3 = __ldcs(p1 + 28); C3 = __ldcs(p2 + 28); dot3(aq0, an0, ax0, a, c); }
        { float4 a = A0, c = C0; A0 = __ldcs(p1 + ADV +  0); C0 = __ldcs(p2 + ADV +  0); dot3(aq1, an1, ax1, a, c); }
        { float4 a = A1, c = C1; A1 = __ldcs(p1 + ADV +  4); C1 = __ldcs(p2 + ADV +  4); dot3(aq1, an1, ax1, a, c); }
        { float4 a = A2, c = C2; A2 = __ldcs(p1 + ADV +  8); C2 = __ldcs(p2 + ADV +  8); dot3(aq1, an1, ax1, a, c); }
        { float4 a = A3, c = C3; A3 = __ldcs(p1 + ADV + 12); C3 = __ldcs(p2 + ADV + 12); dot3(aq1, an1, ax1, a, c); }

        #pragma unroll
        for (int m = 1; m < 4; m <<= 1) {
            aq0 += __shfl_xor_sync(0xffffffffu, aq0, m);
            an0 += __shfl_xor_sync(0xffffffffu, an0, m);
            ax0 += __shfl_xor_sync(0xffffffffu, ax0, m);
            aq1 += __shfl_xor_sync(0xffffffffu, aq1, m);
            an1 += __shfl_xor_sync(0xffffffffu, an1, m);
            ax1 += __shfl_xor_sync(0xffffffffu, ax1, m);
        }
        const float sv0 = ax0 / ((sqrtf(aq0) + 1e-8f) * (sqrtf(an0) + 1e-8f));
        const float sv1 = ax1 / ((sqrtf(aq1) + 1e-8f) * (sqrtf(an1) + 1e-8f));

        float acc = b1s[lane];
        #pragma unroll
        for (int d = 0; d < SIMD; d++) {
            const float v = __shfl_sync(0xffffffffu, (d & 1) ? sv1 : sv0, (d >> 1) << 2);
            acc = fmaf(v, W1fs[d * HIDD + lane], acc);
        }
        float part = w2ss[lane] * tanhf(acc);
        #pragma unroll
        for (int m = 1; m < 32; m <<= 1)
            part += __shfl_xor_sync(0xffffffffu, part, m);
        if (lane == 0) atomicAdd(&out[r / NREG], part + b2s);

        p1 += ADV; p2 += ADV;
        r  += NWARP;
    }

    // ---- peeled final iteration: consume remaining slots, NO refill loads ----
    {
        aq0 = 0.f; an0 = 0.f; ax0 = 0.f; aq1 = 0.f; an1 = 0.f; ax1 = 0.f;
        float4 B0 = __ldcs(p1 + 16), D0 = __ldcs(p2 + 16);
        float4 B1 = __ldcs(p1 + 20), D1 = __ldcs(p2 + 20);
        float4 B2 = __ldcs(p1 + 24), D2 = __ldcs(p2 + 24);
        float4 B3 = __ldcs(p1 + 28), D3 = __ldcs(p2 + 28);
        dot3(aq0, an0, ax0, A0, C0);
        dot3(aq0, an0, ax0, A1, C1);
        dot3(aq0, an0, ax0, A2, C2);
        dot3(aq0, an0, ax0, A3, C3);
        dot3(aq1, an1, ax1, B0, D0);
        dot3(aq1, an1, ax1, B1, D1);
        dot3(aq1, an1, ax1, B2, D2);
        dot3(aq1, an1, ax1, B3, D3);

        #pragma unroll
        for (int m = 1; m < 4; m <<= 1) {
            aq0 += __shfl_xor_sync(0xffffffffu, aq0, m);
            an0 += __shfl_xor_sync(0xffffffffu, an0, m);
            ax0 += __shfl_xor_sync(0xffffffffu, ax0, m);
            aq1 += __shfl_xor_sync(0xffffffffu, aq1, m);
            an1 += __shfl_xor_sync(0xffffffffu, an1, m);
            ax1 += __shfl_xor_sync(0xffffffffu, ax1, m);
        }
        const float sv0 = ax0 / ((sqrtf(aq0) + 1e-8f) * (sqrtf(an0) + 1e-8f));
        const float sv1 = ax1 / ((sqrtf(aq1) + 1e-8f) * (sqrtf(an1) + 1e-8f));

        float acc = b1s[lane];
        #pragma unroll
        for (int d = 0; d < SIMD; d++) {
            const float v = __shfl_sync(0xffffffffu, (d & 1) ? sv1 : sv0, (d >> 1) << 2);
            acc = fmaf(v, W1fs[d * HIDD + lane], acc);
        }
        float part = w2ss[lane] * tanhf(acc);
        #pragma unroll
        for (int m = 1; m < 32; m <<= 1)
            part += __shfl_xor_sync(0xffffffffu, part, m);
        if (lane == 0) atomicAdd(&out[r / NREG], part + b2s);
    }
}

extern "C" void kernel_launch(void* const* d_in, const int* in_sizes, int n_in,
                              void* d_out, int out_size) {
    const int Bn = in_sizes[0] / (NREG * EMBD);
    const int totRows = Bn * NREG;
    cudaMemsetAsync(d_out, 0, (size_t)out_size * sizeof(float));
    prep_kernel<<<1, 512>>>((const float*)d_in[4], (const float*)d_in[5],
                            (const float*)d_in[6], (const float*)d_in[7],
                            (const float*)d_in[8], (const float*)d_in[9],
                            (const float*)d_in[10]);
    const int grid = (GRID * 4 <= totRows) ? GRID : (totRows + 3) / 4;
    simgsmn_main<<<grid, 128>>>((const float*)d_in[0], (const float*)d_in[1],
                                (float*)d_out, totRows);
}